// round 5
// baseline (speedup 1.0000x reference)
#include <cuda_runtime.h>
#include <cstdint>

// ---------------------------------------------------------------------------
// QLSTM fused persistent kernel, v2 (dynamic phases).
//   * each gate uses only W[0,:]  -> theta is a scalar per batch element
//   * _expval(theta,U) = alpha + R*cos(theta - phi)   (3 consts per gate)
//   * f,i,g,o scalars per row -> c[b,:], h[b,:] uniform over hidden dim
// Roles:
//   block 0           : gate constants (all 256 thr), then 128 scalar scans
//   blocks 1..G-1     : PHASE 1 projection (whole chip), then PHASE 2
//                       broadcast via warp-level ticket stealing, gated on
//                       scan progress counters.
// Tight acquire-load spins (no nanosleep on the critical path).
// ---------------------------------------------------------------------------

#define T_STEPS 256
#define BATCH   128
#define ROWS    (T_STEPS * BATCH)   // 32768
#define DIMQ    256
#define CH4     2048                // float4 per bcast chunk (32 KB, 16 rows)

__device__ float4   g_z[ROWS];      // per (t,b): x-projection per gate
__device__ float    g_h[ROWS];      // h scalar per (t,b)
__device__ float    g_cfin[BATCH];  // final c per b
__device__ unsigned g_cnt[T_STEPS]; // rows of z done per t (target 128)
__device__ unsigned g_prog[4];      // scan steps done per scan-warp (target 257)
__device__ unsigned g_ticket;       // bcast chunk ticket

struct Args {
    const float* x;
    const float* W[4];
    const float* b[4];
    const float* P[4];
    float4* out;
    int Wp;   // number of proj warps ((G-1)*8)
    int n4;   // out_size / 4
    int nch;  // number of bcast chunks
};

// ---------------- sync primitives ----------------
__device__ __forceinline__ void red_release(unsigned* p, unsigned v) {
    asm volatile("red.release.gpu.add.u32 [%0], %1;" :: "l"(p), "r"(v) : "memory");
}
__device__ __forceinline__ unsigned ld_rlx(const unsigned* p) {
    unsigned v;
    asm volatile("ld.relaxed.gpu.u32 %0, [%1];" : "=r"(v) : "l"(p) : "memory");
    return v;
}
__device__ __forceinline__ unsigned ld_acq(const unsigned* p) {
    unsigned v;
    asm volatile("ld.acquire.gpu.u32 %0, [%1];" : "=r"(v) : "l"(p) : "memory");
    return v;
}

// ---------------- math helpers ----------------
__device__ __forceinline__ float2 cmul(float2 a, float2 b) {
    return make_float2(a.x * b.x - a.y * b.y, a.x * b.y + a.y * b.x);
}
// prefix-XOR from MSB = CNOT-chain permutation on 8-bit basis index
__device__ __forceinline__ int chain_perm(int k) {
    k ^= k >> 1; k ^= k >> 2; k ^= k >> 4;
    return k & 0xFF;
}
__device__ __forceinline__ float ex2f(float x) {
    float r;
    asm("ex2.approx.f32 %0, %1;" : "=f"(r) : "f"(x));
    return r;
}
__device__ __forceinline__ float rcpf(float x) {
    float r;
    asm("rcp.approx.f32 %0, %1;" : "=f"(r) : "f"(x));
    return r;
}
#define LOG2E 1.44269504088896340736f

// ---------------- init (zero counters each replay) ----------------
__global__ void init_kernel() {
    int i = threadIdx.x;
    g_cnt[i] = 0u;
    if (i < 4) g_prog[i] = 0u;
    if (i == 0) g_ticket = 0u;
}

// ---------------- fused kernel ----------------
__global__ void __launch_bounds__(256, 2) fused_kernel(Args a) {
    const int bid = blockIdx.x;
    const int tid = threadIdx.x;
    const int warp = tid >> 5, lane = tid & 31;

    // ================================ block 0 ================================
    if (bid == 0) {
        __shared__ float2 rot[2][8][2][2];
        __shared__ float2 u0[DIMQ];
        __shared__ float2 u1[DIMQ];
        __shared__ float  rbuf[4][8];
        __shared__ float  s_gate[4][5];   // alpha, R, phi, sW, b0

        // -------- gate constants (4 gates, all 256 threads) --------
        const int k   = tid;
        const int pk0 = chain_perm(k);

        for (int g = 0; g < 4; ++g) {
            __syncthreads();
            const float* P = a.P[g];
            if (k < 16) {
                int l = k >> 3, w = k & 7;
                float phi = P[(l * 8 + w) * 3 + 0];
                float th  = P[(l * 8 + w) * 3 + 1];
                float om  = P[(l * 8 + w) * 3 + 2];
                float s, c;
                __sincosf(0.5f * th, &s, &c);
                float hp = 0.5f * (phi + om);
                float hm = 0.5f * (phi - om);
                float2 ep = make_float2(__cosf(hp), -__sinf(hp));
                float2 em = make_float2(__cosf(hm),  __sinf(hm));
                rot[l][w][0][0] = make_float2( ep.x * c,  ep.y * c);
                rot[l][w][0][1] = make_float2(-em.x * s, -em.y * s);
                rot[l][w][1][0] = make_float2( em.x * s, -em.y * s);
                rot[l][w][1][1] = make_float2( ep.x * c, -ep.y * c);
            }
            __syncthreads();

            float2 a0v = make_float2(1.f, 0.f);
            float2 a1v = make_float2(1.f, 0.f);
            #pragma unroll
            for (int w = 0; w < 8; ++w) {
                int kb = (k >> (7 - w)) & 1;
                a0v = cmul(a0v, rot[0][w][kb][0]);
                a1v = cmul(a1v, rot[0][w][kb][(w == 0) ? 1 : 0]);
            }
            u0[pk0] = a0v;
            u1[pk0] = a1v;
            __syncthreads();

            #pragma unroll
            for (int w = 0; w < 8; ++w) {
                int p = 7 - w, m = 1 << p, kb = (k >> p) & 1;
                float2 x0 = u0[k & ~m], x1 = u0[k | m];
                float2 y0 = u1[k & ~m], y1 = u1[k | m];
                __syncthreads();
                float2 r0 = rot[1][w][kb][0];
                float2 r1 = rot[1][w][kb][1];
                u0[k] = make_float2(r0.x * x0.x - r0.y * x0.y + r1.x * x1.x - r1.y * x1.y,
                                    r0.x * x0.y + r0.y * x0.x + r1.x * x1.y + r1.y * x1.x);
                u1[k] = make_float2(r0.x * y0.x - r0.y * y0.y + r1.x * y1.x - r1.y * y1.y,
                                    r0.x * y0.y + r0.y * y0.x + r1.x * y1.y + r1.y * y1.x);
                __syncthreads();
            }

            float2 c0 = u0[k], c1 = u1[k];
            __syncthreads();
            u0[pk0] = c0; u1[pk0] = c1;
            __syncthreads();
            c0 = u0[k]; c1 = u1[k];

            float z0 = (k < 128) ? 1.f : -1.f;
            float A  = z0 * (c0.x * c0.x + c0.y * c0.y);
            float Bv = z0 * (c1.x * c1.x + c1.y * c1.y);
            float Cv = -2.f * z0 * (c0.y * c1.x - c0.x * c1.y);
            const float* W = a.W[g];
            float sw = W[512 + k] + W[768 + k];

            float vals[4] = {A, Bv, Cv, sw};
            #pragma unroll
            for (int i = 0; i < 4; ++i) {
                float xv = vals[i];
                #pragma unroll
                for (int off = 16; off; off >>= 1)
                    xv += __shfl_xor_sync(0xffffffffu, xv, off);
                if (lane == 0) rbuf[i][warp] = xv;
            }
            __syncthreads();
            if (k == 0) {
                float t[4];
                #pragma unroll
                for (int i = 0; i < 4; ++i) {
                    float s = 0.f;
                    #pragma unroll
                    for (int wv = 0; wv < 8; ++wv) s += rbuf[i][wv];
                    t[i] = s;
                }
                float alpha = 0.5f * (t[0] + t[1]);
                float beta  = 0.5f * (t[0] - t[1]);
                float gamma = 0.5f * t[2];
                float R     = sqrtf(beta * beta + gamma * gamma);
                float phi   = (R > 0.f) ? atan2f(gamma, beta) : 0.f;
                s_gate[g][0] = alpha;
                s_gate[g][1] = R;
                s_gate[g][2] = phi;
                s_gate[g][3] = t[3];
                s_gate[g][4] = a.b[g][0];
            }
        }
        __syncthreads();

        if (tid >= BATCH) return;   // upper half of block 0 done

        // -------- scalar scan (threads 0..127) --------
        const int b = tid, sw_ = b >> 5, slane = b & 31;

        const float swf = s_gate[0][3], swi = s_gate[1][3];
        const float swg = s_gate[2][3], swo = s_gate[3][3];
        const float tbf = s_gate[0][4] - s_gate[0][2];
        const float tbi = s_gate[1][4] - s_gate[1][2];
        const float tbg = s_gate[2][4] - s_gate[2][2];
        const float tbo = s_gate[3][4] - s_gate[3][2];
        // sigmoid(E) = 1 - rcp(ex2(E*log2e)+1);   tanh(E) = 1 - 2*rcp(ex2(2E*log2e)+1)
        const float cRf = s_gate[0][1] * LOG2E, caf = s_gate[0][0] * LOG2E;
        const float cRi = s_gate[1][1] * LOG2E, cai = s_gate[1][0] * LOG2E;
        const float cRg = s_gate[2][1] * (2.f * LOG2E), cag = s_gate[2][0] * (2.f * LOG2E);
        const float cRo = s_gate[3][1] * LOG2E, cao = s_gate[3][0] * LOG2E;

        float4 zb[4], zn[4];
        // wait for group 0 (tight acquire spin)
        while (ld_acq(&g_cnt[0]) < 128u || ld_acq(&g_cnt[1]) < 128u ||
               ld_acq(&g_cnt[2]) < 128u || ld_acq(&g_cnt[3]) < 128u) { }
        #pragma unroll
        for (int j = 0; j < 4; ++j) {
            float4 z = g_z[j * BATCH + b];
            zb[j] = make_float4(z.x + tbf, z.y + tbi, z.z + tbg, z.w + tbo);
        }

        float h = 0.f, cc = 0.f;
        #define QSTEP(ZV, T) { \
            float ef = ex2f(fmaf(cRf, __cosf(fmaf(h, swf, (ZV).x)), caf)); \
            float ei = ex2f(fmaf(cRi, __cosf(fmaf(h, swi, (ZV).y)), cai)); \
            float eg = ex2f(fmaf(cRg, __cosf(fmaf(h, swg, (ZV).z)), cag)); \
            float eo = ex2f(fmaf(cRo, __cosf(fmaf(h, swo, (ZV).w)), cao)); \
            float ff = 1.f -       rcpf(ef + 1.f); \
            float ii = 1.f -       rcpf(ei + 1.f); \
            float gg = 1.f - 2.f * rcpf(eg + 1.f); \
            float oo = 1.f -       rcpf(eo + 1.f); \
            cc = fmaf(ff, cc, ii * gg); \
            float ec = ex2f(cc * (2.f * LOG2E)); \
            h  = oo * (1.f - 2.f * rcpf(ec + 1.f)); \
            g_h[(T) * BATCH + b] = h; }

        for (int t0 = 0; t0 < T_STEPS; t0 += 4) {
            const bool more = (t0 + 4 < T_STEPS);
            unsigned c0 = 128u, c1 = 128u, c2 = 128u, c3 = 128u;
            if (more) {   // acquire loads issued early; latency hides under steps 0-1
                c0 = ld_acq(&g_cnt[t0 + 4]); c1 = ld_acq(&g_cnt[t0 + 5]);
                c2 = ld_acq(&g_cnt[t0 + 6]); c3 = ld_acq(&g_cnt[t0 + 7]);
            }
            QSTEP(zb[0], t0 + 0);
            QSTEP(zb[1], t0 + 1);
            if (more) {
                if ((c0 < 128u) | (c1 < 128u) | (c2 < 128u) | (c3 < 128u)) {
                    while (ld_acq(&g_cnt[t0 + 4]) < 128u || ld_acq(&g_cnt[t0 + 5]) < 128u ||
                           ld_acq(&g_cnt[t0 + 6]) < 128u || ld_acq(&g_cnt[t0 + 7]) < 128u) { }
                }
                #pragma unroll
                for (int j = 0; j < 4; ++j) {
                    float4 z = g_z[(t0 + 4 + j) * BATCH + b];
                    zn[j] = make_float4(z.x + tbf, z.y + tbi, z.z + tbg, z.w + tbo);
                }
            }
            QSTEP(zb[2], t0 + 2);
            QSTEP(zb[3], t0 + 3);
            __syncwarp();
            if (slane == 0) red_release(&g_prog[sw_], 4u);
            if (more) { zb[0] = zn[0]; zb[1] = zn[1]; zb[2] = zn[2]; zb[3] = zn[3]; }
        }
        #undef QSTEP
        g_cfin[b] = cc;
        __syncwarp();
        if (slane == 0) red_release(&g_prog[sw_], 1u);   // prog reaches 257
        return;
    }

    // =============================== workers =================================
    // -------- PHASE 1: projection (all workers) --------
    {
        const int gw = (bid - 1) * 8 + warp;
        const float4* x4 = reinterpret_cast<const float4*>(a.x);

        float4 wv0[4], wv1[4], wv2[4], wv3[4];
        {
            const float4* W0 = reinterpret_cast<const float4*>(a.W[0]);
            const float4* W1 = reinterpret_cast<const float4*>(a.W[1]);
            const float4* W2 = reinterpret_cast<const float4*>(a.W[2]);
            const float4* W3 = reinterpret_cast<const float4*>(a.W[3]);
            #pragma unroll
            for (int it = 0; it < 4; ++it) {
                int e4 = it * 32 + lane;
                wv0[it] = W0[e4]; wv1[it] = W1[e4];
                wv2[it] = W2[e4]; wv3[it] = W3[e4];
            }
        }

        for (int r = gw; r < ROWS; r += a.Wp) {
            const float4* xr = x4 + (size_t)r * 128;
            float s0 = 0.f, s1 = 0.f, s2 = 0.f, s3 = 0.f;
            #pragma unroll
            for (int it = 0; it < 4; ++it) {
                float4 xv = xr[it * 32 + lane];
                s0 = fmaf(xv.x, wv0[it].x, s0); s0 = fmaf(xv.y, wv0[it].y, s0);
                s0 = fmaf(xv.z, wv0[it].z, s0); s0 = fmaf(xv.w, wv0[it].w, s0);
                s1 = fmaf(xv.x, wv1[it].x, s1); s1 = fmaf(xv.y, wv1[it].y, s1);
                s1 = fmaf(xv.z, wv1[it].z, s1); s1 = fmaf(xv.w, wv1[it].w, s1);
                s2 = fmaf(xv.x, wv2[it].x, s2); s2 = fmaf(xv.y, wv2[it].y, s2);
                s2 = fmaf(xv.z, wv2[it].z, s2); s2 = fmaf(xv.w, wv2[it].w, s2);
                s3 = fmaf(xv.x, wv3[it].x, s3); s3 = fmaf(xv.y, wv3[it].y, s3);
                s3 = fmaf(xv.z, wv3[it].z, s3); s3 = fmaf(xv.w, wv3[it].w, s3);
            }
            #pragma unroll
            for (int off = 16; off; off >>= 1) {
                s0 += __shfl_xor_sync(0xffffffffu, s0, off);
                s1 += __shfl_xor_sync(0xffffffffu, s1, off);
                s2 += __shfl_xor_sync(0xffffffffu, s2, off);
                s3 += __shfl_xor_sync(0xffffffffu, s3, off);
            }
            if (lane == 0) {
                g_z[r] = make_float4(s0, s1, s2, s3);
                red_release(&g_cnt[r >> 7], 1u);
            }
        }
    }

    // -------- PHASE 2: broadcast via warp-level ticket stealing --------
    {
        float4* out = a.out;
        for (;;) {
            unsigned tk = 0u;
            if (lane == 0) tk = atomicAdd(&g_ticket, 1u);
            tk = __shfl_sync(0xffffffffu, tk, 0);
            if ((int)tk >= a.nch) break;

            int start = (int)tk * CH4;
            int end   = start + CH4;
            if (end > a.n4) end = a.n4;

            const int lastrow = (end - 1) >> 7;
            unsigned req;
            if (lastrow < ROWS)              req = (unsigned)(lastrow >> 7) + 1u;
            else if (lastrow < ROWS + BATCH) req = 256u;
            else                             req = 257u;

            if (lane == 0) {
                while (ld_rlx(&g_prog[0]) < req || ld_rlx(&g_prog[1]) < req ||
                       ld_rlx(&g_prog[2]) < req || ld_rlx(&g_prog[3]) < req)
                    __nanosleep(128);
                // acquire pass to pair with scan's releases
                while (ld_acq(&g_prog[0]) < req || ld_acq(&g_prog[1]) < req ||
                       ld_acq(&g_prog[2]) < req || ld_acq(&g_prog[3]) < req) { }
            }
            __syncwarp();

            for (int i = start + lane; i < end; i += 32) {
                int row = i >> 7;
                float v;
                if (row < ROWS)              v = g_h[row];
                else if (row < ROWS + BATCH) v = g_h[row - BATCH];      // h at t=255
                else                         v = g_cfin[row - ROWS - BATCH];
                out[i] = make_float4(v, v, v, v);
            }
        }
    }
}

// ---------------- launch ----------------
extern "C" void kernel_launch(void* const* d_in, const int* in_sizes, int n_in,
                              void* d_out, int out_size) {
    static int s_sm = -1;
    if (s_sm < 0) {
        int dev = 0;
        cudaGetDevice(&dev);
        cudaDeviceGetAttribute(&s_sm, cudaDevAttrMultiProcessorCount, dev);
        if (s_sm <= 0) s_sm = 148;
    }
    const int G = 2 * s_sm;   // all blocks resident (launch_bounds(256,2))

    Args a;
    a.x = (const float*)d_in[0];
    a.W[0] = (const float*)d_in[1];  a.b[0] = (const float*)d_in[2];  a.P[0] = (const float*)d_in[3];
    a.W[1] = (const float*)d_in[4];  a.b[1] = (const float*)d_in[5];  a.P[1] = (const float*)d_in[6];
    a.W[2] = (const float*)d_in[7];  a.b[2] = (const float*)d_in[8];  a.P[2] = (const float*)d_in[9];
    a.W[3] = (const float*)d_in[10]; a.b[3] = (const float*)d_in[11]; a.P[3] = (const float*)d_in[12];
    a.out = (float4*)d_out;
    a.Wp  = (G - 1) * 8;
    a.n4  = out_size / 4;
    a.nch = (a.n4 + CH4 - 1) / CH4;

    init_kernel<<<1, 256>>>();
    fused_kernel<<<G, 256>>>(a);
}

// round 6
// speedup vs baseline: 1.8470x; 1.8470x over previous
#include <cuda_runtime.h>
#include <cstdint>

// ---------------------------------------------------------------------------
// QLSTM fused single-kernel, coarse-phase pipeline.
//   * each gate uses only W[0,:]  -> theta is a scalar per batch element
//   * _expval(theta,U) = alpha + R*cos(theta - phi)   (3 consts per gate)
//   * f,i,g,o scalars per row -> c[b,:], h[b,:] uniform over hidden dim
// Phases (separated by a generation grid barrier, 5 uses total):
//   P0 : block 0 = gate constants ; blocks 1..G-1 = projection (67 MB read)
//   k=0..3: block 0 scans steps [64k,64k+64) ; workers bcast chunk k-1
//   PF : all blocks bcast chunk 3 + hx + cx
// All blocks resident: grid = 2 x #SM, __launch_bounds__(256,2).
// ---------------------------------------------------------------------------

#define T_STEPS 256
#define BATCH   128
#define ROWS    (T_STEPS * BATCH)     // 32768
#define DIMQ    256
#define CH_T    64                    // scan steps per pipeline chunk
#define CH4TOT  (CH_T * BATCH * 128)  // float4 per chunk of output = 1048576

__device__ float4   g_z[ROWS];        // per (t,b): x-projection per gate
__device__ float    g_h[ROWS];        // h scalar per (t,b)
__device__ float    g_cfin[BATCH];    // final c per b
__device__ unsigned g_arrive = 0;     // barrier arrivals (self-resetting)
__device__ unsigned g_gen    = 0;     // barrier generation (monotonic)

struct Args {
    const float* x;
    const float* W[4];
    const float* b[4];
    const float* P[4];
    float4* out;
    int G;    // grid size
    int Wp;   // proj warps = (G-1)*8
    int n4;   // out_size / 4
};

// ---------------- sync primitives ----------------
__device__ __forceinline__ unsigned ld_acq(const unsigned* p) {
    unsigned v;
    asm volatile("ld.acquire.gpu.u32 %0, [%1];" : "=r"(v) : "l"(p) : "memory");
    return v;
}
__device__ __forceinline__ unsigned atom_add_rel(unsigned* p, unsigned v) {
    unsigned old;
    asm volatile("atom.add.release.gpu.u32 %0, [%1], %2;"
                 : "=r"(old) : "l"(p), "r"(v) : "memory");
    return old;
}
__device__ __forceinline__ void st_rel(unsigned* p, unsigned v) {
    asm volatile("st.release.gpu.u32 [%0], %1;" :: "l"(p), "r"(v) : "memory");
}
__device__ __forceinline__ void st_rlx(unsigned* p, unsigned v) {
    asm volatile("st.relaxed.gpu.u32 [%0], %1;" :: "l"(p), "r"(v) : "memory");
}

// generation grid barrier; all G blocks, all 256 threads call it.
__device__ __forceinline__ void gridbar(int G) {
    __syncthreads();
    if (threadIdx.x == 0) {
        unsigned gen = ld_acq(&g_gen);
        unsigned prev = atom_add_rel(&g_arrive, 1u);   // releases my prior writes
        if (prev == (unsigned)(G - 1)) {
            st_rlx(&g_arrive, 0u);       // reset for next use
            st_rel(&g_gen, gen + 1u);    // release: reset visible before bump
        } else {
            while (ld_acq(&g_gen) == gen) __nanosleep(64);
        }
    }
    __syncthreads();
}

// ---------------- math helpers ----------------
__device__ __forceinline__ float2 cmul(float2 a, float2 b) {
    return make_float2(a.x * b.x - a.y * b.y, a.x * b.y + a.y * b.x);
}
// prefix-XOR from MSB = CNOT-chain permutation on 8-bit basis index
__device__ __forceinline__ int chain_perm(int k) {
    k ^= k >> 1; k ^= k >> 2; k ^= k >> 4;
    return k & 0xFF;
}
__device__ __forceinline__ float ex2f(float x) {
    float r;
    asm("ex2.approx.f32 %0, %1;" : "=f"(r) : "f"(x));
    return r;
}
__device__ __forceinline__ float rcpf(float x) {
    float r;
    asm("rcp.approx.f32 %0, %1;" : "=f"(r) : "f"(x));
    return r;
}
#define LOG2E 1.44269504088896340736f

// ---------------- fused kernel ----------------
__global__ void __launch_bounds__(256, 2) fused_kernel(Args a) {
    const int bid  = blockIdx.x;
    const int tid  = threadIdx.x;
    const int warp = tid >> 5, lane = tid & 31;

    __shared__ float2 rot[2][8][2][2];
    __shared__ float2 u0[DIMQ];
    __shared__ float2 u1[DIMQ];
    __shared__ float  rbuf[4][8];
    __shared__ float  s_gate[4][5];   // alpha, R, phi, sW, b0

    // ========================= PHASE 0 =========================
    if (bid == 0) {
        // -------- gate constants (all 256 threads, 4 gates) --------
        const int k   = tid;
        const int pk0 = chain_perm(k);

        for (int g = 0; g < 4; ++g) {
            __syncthreads();
            const float* P = a.P[g];
            if (k < 16) {
                int l = k >> 3, w = k & 7;
                float phi = P[(l * 8 + w) * 3 + 0];
                float th  = P[(l * 8 + w) * 3 + 1];
                float om  = P[(l * 8 + w) * 3 + 2];
                float s, c;
                __sincosf(0.5f * th, &s, &c);
                float hp = 0.5f * (phi + om);
                float hm = 0.5f * (phi - om);
                float2 ep = make_float2(__cosf(hp), -__sinf(hp));
                float2 em = make_float2(__cosf(hm),  __sinf(hm));
                rot[l][w][0][0] = make_float2( ep.x * c,  ep.y * c);
                rot[l][w][0][1] = make_float2(-em.x * s, -em.y * s);
                rot[l][w][1][0] = make_float2( em.x * s, -em.y * s);
                rot[l][w][1][1] = make_float2( ep.x * c, -ep.y * c);
            }
            __syncthreads();

            float2 a0v = make_float2(1.f, 0.f);
            float2 a1v = make_float2(1.f, 0.f);
            #pragma unroll
            for (int w = 0; w < 8; ++w) {
                int kb = (k >> (7 - w)) & 1;
                a0v = cmul(a0v, rot[0][w][kb][0]);
                a1v = cmul(a1v, rot[0][w][kb][(w == 0) ? 1 : 0]);
            }
            u0[pk0] = a0v;
            u1[pk0] = a1v;
            __syncthreads();

            #pragma unroll
            for (int w = 0; w < 8; ++w) {
                int p = 7 - w, m = 1 << p, kb = (k >> p) & 1;
                float2 x0 = u0[k & ~m], x1 = u0[k | m];
                float2 y0 = u1[k & ~m], y1 = u1[k | m];
                __syncthreads();
                float2 r0 = rot[1][w][kb][0];
                float2 r1 = rot[1][w][kb][1];
                u0[k] = make_float2(r0.x * x0.x - r0.y * x0.y + r1.x * x1.x - r1.y * x1.y,
                                    r0.x * x0.y + r0.y * x0.x + r1.x * x1.y + r1.y * x1.x);
                u1[k] = make_float2(r0.x * y0.x - r0.y * y0.y + r1.x * y1.x - r1.y * y1.y,
                                    r0.x * y0.y + r0.y * y0.x + r1.x * y1.y + r1.y * y1.x);
                __syncthreads();
            }

            float2 c0 = u0[k], c1 = u1[k];
            __syncthreads();
            u0[pk0] = c0; u1[pk0] = c1;
            __syncthreads();
            c0 = u0[k]; c1 = u1[k];

            float z0 = (k < 128) ? 1.f : -1.f;
            float A  = z0 * (c0.x * c0.x + c0.y * c0.y);
            float Bv = z0 * (c1.x * c1.x + c1.y * c1.y);
            float Cv = -2.f * z0 * (c0.y * c1.x - c0.x * c1.y);
            const float* W = a.W[g];
            float sw = W[512 + k] + W[768 + k];

            float vals[4] = {A, Bv, Cv, sw};
            #pragma unroll
            for (int i = 0; i < 4; ++i) {
                float xv = vals[i];
                #pragma unroll
                for (int off = 16; off; off >>= 1)
                    xv += __shfl_xor_sync(0xffffffffu, xv, off);
                if (lane == 0) rbuf[i][warp] = xv;
            }
            __syncthreads();
            if (k == 0) {
                float t[4];
                #pragma unroll
                for (int i = 0; i < 4; ++i) {
                    float s = 0.f;
                    #pragma unroll
                    for (int wv = 0; wv < 8; ++wv) s += rbuf[i][wv];
                    t[i] = s;
                }
                float alpha = 0.5f * (t[0] + t[1]);
                float beta  = 0.5f * (t[0] - t[1]);
                float gamma = 0.5f * t[2];
                float R     = sqrtf(beta * beta + gamma * gamma);
                float phi   = (R > 0.f) ? atan2f(gamma, beta) : 0.f;
                s_gate[g][0] = alpha;
                s_gate[g][1] = R;
                s_gate[g][2] = phi;
                s_gate[g][3] = t[3];
                s_gate[g][4] = a.b[g][0];
            }
        }
        __syncthreads();
    } else {
        // -------- projection: z[t,b] = x[t,b,:] . W[g][0,:512] --------
        const int gw = (bid - 1) * 8 + warp;
        const float4* x4 = reinterpret_cast<const float4*>(a.x);

        float4 wv0[4], wv1[4], wv2[4], wv3[4];
        {
            const float4* W0 = reinterpret_cast<const float4*>(a.W[0]);
            const float4* W1 = reinterpret_cast<const float4*>(a.W[1]);
            const float4* W2 = reinterpret_cast<const float4*>(a.W[2]);
            const float4* W3 = reinterpret_cast<const float4*>(a.W[3]);
            #pragma unroll
            for (int it = 0; it < 4; ++it) {
                int e4 = it * 32 + lane;
                wv0[it] = W0[e4]; wv1[it] = W1[e4];
                wv2[it] = W2[e4]; wv3[it] = W3[e4];
            }
        }

        for (int r = gw; r < ROWS; r += a.Wp) {
            const float4* xr = x4 + (size_t)r * 128;
            float s0 = 0.f, s1 = 0.f, s2 = 0.f, s3 = 0.f;
            #pragma unroll
            for (int it = 0; it < 4; ++it) {
                float4 xv = xr[it * 32 + lane];
                s0 = fmaf(xv.x, wv0[it].x, s0); s0 = fmaf(xv.y, wv0[it].y, s0);
                s0 = fmaf(xv.z, wv0[it].z, s0); s0 = fmaf(xv.w, wv0[it].w, s0);
                s1 = fmaf(xv.x, wv1[it].x, s1); s1 = fmaf(xv.y, wv1[it].y, s1);
                s1 = fmaf(xv.z, wv1[it].z, s1); s1 = fmaf(xv.w, wv1[it].w, s1);
                s2 = fmaf(xv.x, wv2[it].x, s2); s2 = fmaf(xv.y, wv2[it].y, s2);
                s2 = fmaf(xv.z, wv2[it].z, s2); s2 = fmaf(xv.w, wv2[it].w, s2);
                s3 = fmaf(xv.x, wv3[it].x, s3); s3 = fmaf(xv.y, wv3[it].y, s3);
                s3 = fmaf(xv.z, wv3[it].z, s3); s3 = fmaf(xv.w, wv3[it].w, s3);
            }
            #pragma unroll
            for (int off = 16; off; off >>= 1) {
                s0 += __shfl_xor_sync(0xffffffffu, s0, off);
                s1 += __shfl_xor_sync(0xffffffffu, s1, off);
                s2 += __shfl_xor_sync(0xffffffffu, s2, off);
                s3 += __shfl_xor_sync(0xffffffffu, s3, off);
            }
            if (lane == 0) g_z[r] = make_float4(s0, s1, s2, s3);
        }
    }

    gridbar(a.G);   // proj + consts complete

    // ========================= PIPELINE: 4 chunks =========================
    // scan-side constants (block 0, threads < BATCH)
    float swf = 0.f, swi = 0.f, swg = 0.f, swo = 0.f;
    float tbf = 0.f, tbi = 0.f, tbg = 0.f, tbo = 0.f;
    float cRf = 0.f, caf = 0.f, cRi = 0.f, cai = 0.f;
    float cRg = 0.f, cag = 0.f, cRo = 0.f, cao = 0.f;
    float h = 0.f, cc = 0.f;
    const bool is_scan = (bid == 0 && tid < BATCH);
    if (is_scan) {
        swf = s_gate[0][3]; swi = s_gate[1][3]; swg = s_gate[2][3]; swo = s_gate[3][3];
        tbf = s_gate[0][4] - s_gate[0][2];
        tbi = s_gate[1][4] - s_gate[1][2];
        tbg = s_gate[2][4] - s_gate[2][2];
        tbo = s_gate[3][4] - s_gate[3][2];
        cRf = s_gate[0][1] * LOG2E;         caf = s_gate[0][0] * LOG2E;
        cRi = s_gate[1][1] * LOG2E;         cai = s_gate[1][0] * LOG2E;
        cRg = s_gate[2][1] * (2.f * LOG2E); cag = s_gate[2][0] * (2.f * LOG2E);
        cRo = s_gate[3][1] * LOG2E;         cao = s_gate[3][0] * LOG2E;
    }

    #define QSTEP(ZV, T) { \
        float ef = ex2f(fmaf(cRf, __cosf(fmaf(h, swf, (ZV).x)), caf)); \
        float ei = ex2f(fmaf(cRi, __cosf(fmaf(h, swi, (ZV).y)), cai)); \
        float eg = ex2f(fmaf(cRg, __cosf(fmaf(h, swg, (ZV).z)), cag)); \
        float eo = ex2f(fmaf(cRo, __cosf(fmaf(h, swo, (ZV).w)), cao)); \
        float ff = 1.f -       rcpf(ef + 1.f); \
        float ii = 1.f -       rcpf(ei + 1.f); \
        float gg = 1.f - 2.f * rcpf(eg + 1.f); \
        float oo = 1.f -       rcpf(eo + 1.f); \
        cc = fmaf(ff, cc, ii * gg); \
        float ec = ex2f(cc * (2.f * LOG2E)); \
        h  = oo * (1.f - 2.f * rcpf(ec + 1.f)); \
        g_h[(T) * BATCH + b] = h; }

    for (int kch = 0; kch < 4; ++kch) {
        if (is_scan) {
            const int b = tid;
            const int tbase = kch * CH_T;
            float4 zb[4], zn[4];
            #pragma unroll
            for (int j = 0; j < 4; ++j) {
                float4 z = g_z[(tbase + j) * BATCH + b];
                zb[j] = make_float4(z.x + tbf, z.y + tbi, z.z + tbg, z.w + tbo);
            }
            #pragma unroll
            for (int j = 0; j < 4; ++j) {
                float4 z = g_z[(tbase + 4 + j) * BATCH + b];
                zn[j] = make_float4(z.x + tbf, z.y + tbi, z.z + tbg, z.w + tbo);
            }
            for (int g4 = 0; g4 < CH_T; g4 += 4) {
                float4 znn[4];
                const bool more = (g4 + 8 < CH_T);
                if (more) {   // load 2 groups ahead: ~1040 cyc of slack vs ~260 L2 latency
                    #pragma unroll
                    for (int j = 0; j < 4; ++j) {
                        float4 z = g_z[(tbase + g4 + 8 + j) * BATCH + b];
                        znn[j] = make_float4(z.x + tbf, z.y + tbi, z.z + tbg, z.w + tbo);
                    }
                }
                QSTEP(zb[0], tbase + g4 + 0);
                QSTEP(zb[1], tbase + g4 + 1);
                QSTEP(zb[2], tbase + g4 + 2);
                QSTEP(zb[3], tbase + g4 + 3);
                zb[0] = zn[0]; zb[1] = zn[1]; zb[2] = zn[2]; zb[3] = zn[3];
                if (more) { zn[0] = znn[0]; zn[1] = znn[1]; zn[2] = znn[2]; zn[3] = znn[3]; }
            }
            if (kch == 3) g_cfin[b] = cc;
        } else if (bid > 0 && kch > 0) {
            // broadcast chunk kch-1 (rows fully written, barrier-ordered)
            float4* out = a.out;
            const int start = (kch - 1) * CH4TOT;
            const int end   = kch * CH4TOT;
            const int stride = (a.G - 1) * 256;
            for (int i = start + (bid - 1) * 256 + tid; i < end; i += stride) {
                float v = g_h[i >> 7];
                out[i] = make_float4(v, v, v, v);
            }
        }
        gridbar(a.G);
    }
    #undef QSTEP

    // ========================= FINAL: chunk 3 + hx + cx =========================
    {
        float4* out = a.out;
        const int start = 3 * CH4TOT;
        const int stride = a.G * 256;
        for (int i = start + bid * 256 + tid; i < a.n4; i += stride) {
            int row = i >> 7;
            float v;
            if (row < ROWS)              v = g_h[row];
            else if (row < ROWS + BATCH) v = g_h[row - BATCH];          // hx = h at t=255
            else                         v = g_cfin[row - ROWS - BATCH]; // cx
            out[i] = make_float4(v, v, v, v);
        }
    }
}

// ---------------- launch ----------------
extern "C" void kernel_launch(void* const* d_in, const int* in_sizes, int n_in,
                              void* d_out, int out_size) {
    static int s_sm = -1;
    if (s_sm < 0) {
        int dev = 0;
        cudaGetDevice(&dev);
        cudaDeviceGetAttribute(&s_sm, cudaDevAttrMultiProcessorCount, dev);
        if (s_sm <= 0) s_sm = 148;
    }
    const int G = 2 * s_sm;   // all blocks resident (launch_bounds(256,2))

    Args a;
    a.x = (const float*)d_in[0];
    a.W[0] = (const float*)d_in[1];  a.b[0] = (const float*)d_in[2];  a.P[0] = (const float*)d_in[3];
    a.W[1] = (const float*)d_in[4];  a.b[1] = (const float*)d_in[5];  a.P[1] = (const float*)d_in[6];
    a.W[2] = (const float*)d_in[7];  a.b[2] = (const float*)d_in[8];  a.P[2] = (const float*)d_in[9];
    a.W[3] = (const float*)d_in[10]; a.b[3] = (const float*)d_in[11]; a.P[3] = (const float*)d_in[12];
    a.out = (float4*)d_out;
    a.G   = G;
    a.Wp  = (G - 1) * 8;
    a.n4  = out_size / 4;

    fused_kernel<<<G, 256>>>(a);
}

// round 7
// speedup vs baseline: 2.1250x; 1.1505x over previous
#include <cuda_runtime.h>
#include <cstdint>

// ---------------------------------------------------------------------------
// QLSTM fused persistent kernel, v3: pure dataflow, no grid barriers.
//   * each gate uses only W[0,:]  -> theta is a scalar per batch element
//   * _expval(theta,U) = alpha + R*cos(theta - phi), E in [-1,1]
//   * f,i,g,o scalars per row -> c[b,:], h[b,:] uniform over hidden dim
// Roles:
//   block 0       : gate constants (256 thr), then 128 scalar scans.
//                   Consumes z per 32-step chunk via credit counters;
//                   publishes progress via one release word g_done.
//   blocks 1..G-1 : projection (contiguous row blocks, credit bumps),
//                   then chunk-by-chunk broadcast gated on g_done.
// ---------------------------------------------------------------------------

#define T_STEPS 256
#define BATCH   128
#define ROWS    (T_STEPS * BATCH)     // 32768
#define DIMQ    256
#define NCH     8
#define CH_T    32                    // scan steps per chunk
#define CHROWS  (CH_T * BATCH)        // 4096 z-rows per chunk
#define REG4    (CHROWS * 128)        // float4 of output per chunk = 524288

__device__ float4   g_z[ROWS];        // per (t,b): x-projection per gate (+bias-phi)
__device__ float    g_h[ROWS];        // h scalar per (t,b)
__device__ float    g_cfin[BATCH];    // final c per b
__device__ unsigned g_zcnt[NCH];      // z rows completed per chunk (target 4096)
__device__ unsigned g_done;           // scan chunks completed (target 8)

struct Args {
    const float* x;
    const float* W[4];
    const float* b[4];
    const float* P[4];
    float4* out;
    int G;     // grid size
    int Wp;    // proj warps = (G-1)*8
    int RPW;   // rows per proj warp
    int n4;    // out_size / 4
};

// ---------------- sync primitives ----------------
__device__ __forceinline__ void red_release(unsigned* p, unsigned v) {
    asm volatile("red.release.gpu.add.u32 [%0], %1;" :: "l"(p), "r"(v) : "memory");
}
__device__ __forceinline__ unsigned ld_acq(const unsigned* p) {
    unsigned v;
    asm volatile("ld.acquire.gpu.u32 %0, [%1];" : "=r"(v) : "l"(p) : "memory");
    return v;
}
__device__ __forceinline__ void publish(unsigned* p, unsigned v) {
    asm volatile("fence.acq_rel.gpu;" ::: "memory");
    asm volatile("st.relaxed.gpu.u32 [%0], %1;" :: "l"(p), "r"(v) : "memory");
}

// ---------------- math helpers ----------------
__device__ __forceinline__ float2 cmul(float2 a, float2 b) {
    return make_float2(a.x * b.x - a.y * b.y, a.x * b.y + a.y * b.x);
}
__device__ __forceinline__ int chain_perm(int k) {   // CNOT chain = prefix-XOR
    k ^= k >> 1; k ^= k >> 2; k ^= k >> 4;
    return k & 0xFF;
}
__device__ __forceinline__ float rcpf(float x) {
    float r;
    asm("rcp.approx.f32 %0, %1;" : "=f"(r) : "f"(x));
    return r;
}
// sigmoid(x), |x|<=1: odd Taylor deg 9, err <= 2.2e-6
__device__ __forceinline__ float sig_poly(float x) {
    float y = x * x;
    float p = fmaf(y,  2.1356999e-5f, -2.1084600e-4f);
    p = fmaf(y, p,  2.0833333e-3f);
    p = fmaf(y, p, -2.0833333e-2f);
    p = fmaf(y, p,  2.5e-1f);
    return fmaf(x, p, 0.5f);
}
// tanh(x), |x|<~2.6: [7/6] Pade, err <= ~6e-6
__device__ __forceinline__ float tanh_pade(float x) {
    float y = x * x;
    float n = fmaf(y, fmaf(y, 21.f, 1260.f), 10395.f);
    float d = fmaf(y, fmaf(y, fmaf(y, 1.f, 210.f), 4725.f), 10395.f);
    return (x * n) * rcpf(d);
}

// ---------------- init (reset counters each replay) ----------------
__global__ void init_kernel() {
    int i = threadIdx.x;
    if (i < NCH) g_zcnt[i] = 0u;
    if (i == NCH) g_done = 0u;
}

// ---------------- fused kernel ----------------
__global__ void __launch_bounds__(256, 2) fused_kernel(Args a) {
    const int bid  = blockIdx.x;
    const int tid  = threadIdx.x;
    const int warp = tid >> 5, lane = tid & 31;

    // ============================ block 0: consts + scan ============================
    if (bid == 0) {
        __shared__ float2 rot[2][8][2][2];
        __shared__ float2 u0[DIMQ];
        __shared__ float2 u1[DIMQ];
        __shared__ float  rbuf[4][8];
        __shared__ float  s_gate[4][5];   // alpha, R, phi, sW, b0

        const int k   = tid;
        const int pk0 = chain_perm(k);

        for (int g = 0; g < 4; ++g) {
            __syncthreads();
            const float* P = a.P[g];
            if (k < 16) {
                int l = k >> 3, w = k & 7;
                float phi = P[(l * 8 + w) * 3 + 0];
                float th  = P[(l * 8 + w) * 3 + 1];
                float om  = P[(l * 8 + w) * 3 + 2];
                float s, c;
                __sincosf(0.5f * th, &s, &c);
                float hp = 0.5f * (phi + om);
                float hm = 0.5f * (phi - om);
                float2 ep = make_float2(__cosf(hp), -__sinf(hp));
                float2 em = make_float2(__cosf(hm),  __sinf(hm));
                rot[l][w][0][0] = make_float2( ep.x * c,  ep.y * c);
                rot[l][w][0][1] = make_float2(-em.x * s, -em.y * s);
                rot[l][w][1][0] = make_float2( em.x * s, -em.y * s);
                rot[l][w][1][1] = make_float2( ep.x * c, -ep.y * c);
            }
            __syncthreads();

            float2 a0v = make_float2(1.f, 0.f);
            float2 a1v = make_float2(1.f, 0.f);
            #pragma unroll
            for (int w = 0; w < 8; ++w) {
                int kb = (k >> (7 - w)) & 1;
                a0v = cmul(a0v, rot[0][w][kb][0]);
                a1v = cmul(a1v, rot[0][w][kb][(w == 0) ? 1 : 0]);
            }
            u0[pk0] = a0v;
            u1[pk0] = a1v;
            __syncthreads();

            #pragma unroll
            for (int w = 0; w < 8; ++w) {
                int p = 7 - w, m = 1 << p, kb = (k >> p) & 1;
                float2 x0 = u0[k & ~m], x1 = u0[k | m];
                float2 y0 = u1[k & ~m], y1 = u1[k | m];
                __syncthreads();
                float2 r0 = rot[1][w][kb][0];
                float2 r1 = rot[1][w][kb][1];
                u0[k] = make_float2(r0.x * x0.x - r0.y * x0.y + r1.x * x1.x - r1.y * x1.y,
                                    r0.x * x0.y + r0.y * x0.x + r1.x * x1.y + r1.y * x1.x);
                u1[k] = make_float2(r0.x * y0.x - r0.y * y0.y + r1.x * y1.x - r1.y * y1.y,
                                    r0.x * y0.y + r0.y * y0.x + r1.x * y1.y + r1.y * y1.x);
                __syncthreads();
            }

            float2 c0 = u0[k], c1 = u1[k];
            __syncthreads();
            u0[pk0] = c0; u1[pk0] = c1;
            __syncthreads();
            c0 = u0[k]; c1 = u1[k];

            float z0 = (k < 128) ? 1.f : -1.f;
            float A  = z0 * (c0.x * c0.x + c0.y * c0.y);
            float Bv = z0 * (c1.x * c1.x + c1.y * c1.y);
            float Cv = -2.f * z0 * (c0.y * c1.x - c0.x * c1.y);
            const float* W = a.W[g];
            float sw = W[512 + k] + W[768 + k];

            float vals[4] = {A, Bv, Cv, sw};
            #pragma unroll
            for (int i = 0; i < 4; ++i) {
                float xv = vals[i];
                #pragma unroll
                for (int off = 16; off; off >>= 1)
                    xv += __shfl_xor_sync(0xffffffffu, xv, off);
                if (lane == 0) rbuf[i][warp] = xv;
            }
            __syncthreads();
            if (k == 0) {
                float t[4];
                #pragma unroll
                for (int i = 0; i < 4; ++i) {
                    float s = 0.f;
                    #pragma unroll
                    for (int wv = 0; wv < 8; ++wv) s += rbuf[i][wv];
                    t[i] = s;
                }
                float alpha = 0.5f * (t[0] + t[1]);
                float beta  = 0.5f * (t[0] - t[1]);
                float gamma = 0.5f * t[2];
                float R     = sqrtf(beta * beta + gamma * gamma);
                float phi   = (R > 0.f) ? atan2f(gamma, beta) : 0.f;
                s_gate[g][0] = alpha;
                s_gate[g][1] = R;
                s_gate[g][2] = phi;
                s_gate[g][3] = t[3];
                s_gate[g][4] = a.b[g][0];
            }
        }
        __syncthreads();

        if (tid >= BATCH) return;   // warps 4-7 of block 0 are done

        // -------- scalar scan (threads 0..127), chunked, credit-gated --------
        const int b = tid;
        const float af = s_gate[0][0], Rf = s_gate[0][1], swf = s_gate[0][3];
        const float ai = s_gate[1][0], Ri = s_gate[1][1], swi = s_gate[1][3];
        const float ag = s_gate[2][0], Rg = s_gate[2][1], swg = s_gate[2][3];
        const float ao = s_gate[3][0], Ro = s_gate[3][1], swo = s_gate[3][3];
        const float tbf = s_gate[0][4] - s_gate[0][2];
        const float tbi = s_gate[1][4] - s_gate[1][2];
        const float tbg = s_gate[2][4] - s_gate[2][2];
        const float tbo = s_gate[3][4] - s_gate[3][2];

        float h = 0.f, cc = 0.f;

        #define QSTEP(ZV, T) { \
            float vf = __cosf(fmaf(h, swf, (ZV).x)); \
            float vi = __cosf(fmaf(h, swi, (ZV).y)); \
            float vg = __cosf(fmaf(h, swg, (ZV).z)); \
            float vo = __cosf(fmaf(h, swo, (ZV).w)); \
            float ff = sig_poly(fmaf(Rf, vf, af)); \
            float ii = sig_poly(fmaf(Ri, vi, ai)); \
            float gg = tanh_pade(fmaf(Rg, vg, ag)); \
            float oo = sig_poly(fmaf(Ro, vo, ao)); \
            cc = fmaf(ff, cc, ii * gg); \
            h  = oo * tanh_pade(cc); \
            g_h[(T) * BATCH + b] = h; }

        for (int c = 0; c < NCH; ++c) {
            // tight spin: only 4 warps poll; proj outruns the scan after chunk 0
            while (ld_acq(&g_zcnt[c]) < (unsigned)CHROWS) {}

            const int tbase = c * CH_T;
            float4 zb[4], zn[4];
            #pragma unroll
            for (int j = 0; j < 4; ++j) {
                float4 z = g_z[(tbase + j) * BATCH + b];
                zb[j] = make_float4(z.x + tbf, z.y + tbi, z.z + tbg, z.w + tbo);
            }
            #pragma unroll
            for (int j = 0; j < 4; ++j) {
                float4 z = g_z[(tbase + 4 + j) * BATCH + b];
                zn[j] = make_float4(z.x + tbf, z.y + tbi, z.z + tbg, z.w + tbo);
            }
            for (int g4 = 0; g4 < CH_T; g4 += 4) {
                float4 znn[4];
                const bool more = (g4 + 8 < CH_T);
                if (more) {   // 8-step-deep prefetch: ~900 cyc slack vs L2 latency
                    #pragma unroll
                    for (int j = 0; j < 4; ++j) {
                        float4 z = g_z[(tbase + g4 + 8 + j) * BATCH + b];
                        znn[j] = make_float4(z.x + tbf, z.y + tbi, z.z + tbg, z.w + tbo);
                    }
                }
                QSTEP(zb[0], tbase + g4 + 0);
                QSTEP(zb[1], tbase + g4 + 1);
                QSTEP(zb[2], tbase + g4 + 2);
                QSTEP(zb[3], tbase + g4 + 3);
                zb[0] = zn[0]; zb[1] = zn[1]; zb[2] = zn[2]; zb[3] = zn[3];
                if (more) { zn[0] = znn[0]; zn[1] = znn[1]; zn[2] = znn[2]; zn[3] = znn[3]; }
            }
            if (c == NCH - 1) g_cfin[b] = cc;

            asm volatile("bar.sync 1, 128;" ::: "memory");   // all 4 scan warps done
            if (tid == 0) publish(&g_done, (unsigned)(c + 1));
        }
        #undef QSTEP
        return;
    }

    // ============================ workers ============================
    // -------- PHASE 1: projection, contiguous row blocks + credits --------
    {
        const int gw = (bid - 1) * 8 + warp;
        int lo = gw * a.RPW;
        int hi = lo + a.RPW;
        if (hi > ROWS) hi = ROWS;

        if (lo < ROWS) {
            const float4* x4 = reinterpret_cast<const float4*>(a.x);
            float4 wv0[4], wv1[4], wv2[4], wv3[4];
            {
                const float4* W0 = reinterpret_cast<const float4*>(a.W[0]);
                const float4* W1 = reinterpret_cast<const float4*>(a.W[1]);
                const float4* W2 = reinterpret_cast<const float4*>(a.W[2]);
                const float4* W3 = reinterpret_cast<const float4*>(a.W[3]);
                #pragma unroll
                for (int it = 0; it < 4; ++it) {
                    int e4 = it * 32 + lane;
                    wv0[it] = W0[e4]; wv1[it] = W1[e4];
                    wv2[it] = W2[e4]; wv3[it] = W3[e4];
                }
            }

            int r = lo;
            while (r < hi) {
                const int c = r / CHROWS;
                int cend = (c + 1) * CHROWS;
                if (cend > hi) cend = hi;
                const int ndone = cend - r;
                for (; r < cend; ++r) {
                    const float4* xr = x4 + (size_t)r * 128;
                    float s0 = 0.f, s1 = 0.f, s2 = 0.f, s3 = 0.f;
                    #pragma unroll
                    for (int it = 0; it < 4; ++it) {
                        float4 xv = xr[it * 32 + lane];
                        s0 = fmaf(xv.x, wv0[it].x, s0); s0 = fmaf(xv.y, wv0[it].y, s0);
                        s0 = fmaf(xv.z, wv0[it].z, s0); s0 = fmaf(xv.w, wv0[it].w, s0);
                        s1 = fmaf(xv.x, wv1[it].x, s1); s1 = fmaf(xv.y, wv1[it].y, s1);
                        s1 = fmaf(xv.z, wv1[it].z, s1); s1 = fmaf(xv.w, wv1[it].w, s1);
                        s2 = fmaf(xv.x, wv2[it].x, s2); s2 = fmaf(xv.y, wv2[it].y, s2);
                        s2 = fmaf(xv.z, wv2[it].z, s2); s2 = fmaf(xv.w, wv2[it].w, s2);
                        s3 = fmaf(xv.x, wv3[it].x, s3); s3 = fmaf(xv.y, wv3[it].y, s3);
                        s3 = fmaf(xv.z, wv3[it].z, s3); s3 = fmaf(xv.w, wv3[it].w, s3);
                    }
                    #pragma unroll
                    for (int off = 16; off; off >>= 1) {
                        s0 += __shfl_xor_sync(0xffffffffu, s0, off);
                        s1 += __shfl_xor_sync(0xffffffffu, s1, off);
                        s2 += __shfl_xor_sync(0xffffffffu, s2, off);
                        s3 += __shfl_xor_sync(0xffffffffu, s3, off);
                    }
                    if (lane == 0) g_z[r] = make_float4(s0, s1, s2, s3);
                }
                if (lane == 0) red_release(&g_zcnt[c], (unsigned)ndone);
            }
        }
    }

    // -------- PHASE 2: broadcast, chunk-by-chunk gated on g_done --------
    {
        __shared__ unsigned s_go;   // dummy sync cell not needed; use syncthreads
        (void)s_go;
        float4* out = a.out;
        const int stride = (a.G - 1) * 256;
        const int self   = (bid - 1) * 256 + tid;

        for (int c = 0; c < NCH; ++c) {
            if (tid == 0) {
                while (ld_acq(&g_done) < (unsigned)(c + 1)) __nanosleep(128);
            }
            __syncthreads();
            const int base = c * REG4;
            const int end  = base + REG4;
            #pragma unroll 2
            for (int i = base + self; i < end; i += stride) {
                float v = g_h[i >> 7];
                out[i] = make_float4(v, v, v, v);
            }
        }
        // hx + cx (g_done==8 implies cfin + all h published)
        const int base = NCH * REG4;   // == ROWS*128
        for (int i = base + self; i < a.n4; i += stride) {
            int row = i >> 7;
            float v;
            if (row < ROWS + BATCH) v = g_h[row - BATCH];            // hx = h at t=255
            else                    v = g_cfin[row - ROWS - BATCH];  // cx
            out[i] = make_float4(v, v, v, v);
        }
    }
}

// ---------------- launch ----------------
extern "C" void kernel_launch(void* const* d_in, const int* in_sizes, int n_in,
                              void* d_out, int out_size) {
    static int s_sm = -1;
    if (s_sm < 0) {
        int dev = 0;
        cudaGetDevice(&dev);
        cudaDeviceGetAttribute(&s_sm, cudaDevAttrMultiProcessorCount, dev);
        if (s_sm <= 0) s_sm = 148;
    }
    const int G  = 2 * s_sm;            // all blocks resident
    const int Wp = (G - 1) * 8;

    Args a;
    a.x = (const float*)d_in[0];
    a.W[0] = (const float*)d_in[1];  a.b[0] = (const float*)d_in[2];  a.P[0] = (const float*)d_in[3];
    a.W[1] = (const float*)d_in[4];  a.b[1] = (const float*)d_in[5];  a.P[1] = (const float*)d_in[6];
    a.W[2] = (const float*)d_in[7];  a.b[2] = (const float*)d_in[8];  a.P[2] = (const float*)d_in[9];
    a.W[3] = (const float*)d_in[10]; a.b[3] = (const float*)d_in[11]; a.P[3] = (const float*)d_in[12];
    a.out = (float4*)d_out;
    a.G   = G;
    a.Wp  = Wp;
    a.RPW = (ROWS + Wp - 1) / Wp;
    a.n4  = out_size / 4;

    init_kernel<<<1, 32>>>();
    fused_kernel<<<G, 256>>>(a);
}

// round 8
// speedup vs baseline: 2.2259x; 1.0475x over previous
#include <cuda_runtime.h>
#include <cstdint>

// ---------------------------------------------------------------------------
// QLSTM fused persistent kernel, v4: dataflow + chunk-major projection.
//   * each gate uses only W[0,:]  -> theta is a scalar per batch element
//   * _expval(theta,U) = alpha + R*cos(theta - phi), E in [-1,1]
//   * f,i,g,o scalars per row -> c[b,:], h[b,:] uniform over hidden dim
// Roles:
//   block 0       : gate constants (256 thr), then 128 scalar scans,
//                   chunk-gated on credit counters, publishing g_done.
//   blocks 1..G-1 : projection in CHUNK-MAJOR order (chunk c of z completes
//                   at ~ (c+1)/8 of proj time -> scan starts ~1.5us in),
//                   then chunk-by-chunk broadcast gated on g_done.
// ---------------------------------------------------------------------------

#define T_STEPS 256
#define BATCH   128
#define ROWS    (T_STEPS * BATCH)     // 32768
#define DIMQ    256
#define NCH     8
#define CH_T    32                    // scan steps per chunk
#define CHROWS  (CH_T * BATCH)        // 4096 z-rows per chunk
#define REG4    (CHROWS * 128)        // float4 of output per chunk = 524288

__device__ float4   g_z[ROWS];        // per (t,b): x-projection per gate
__device__ float    g_h[ROWS];        // h scalar per (t,b)
__device__ float    g_cfin[BATCH];    // final c per b
__device__ unsigned g_zcnt[NCH];      // z rows completed per chunk (target 4096)
__device__ unsigned g_done;           // scan chunks completed (target 8)

struct Args {
    const float* x;
    const float* W[4];
    const float* b[4];
    const float* P[4];
    float4* out;
    int G;     // grid size
    int Wp;    // proj warps = (G-1)*8
    int n4;    // out_size / 4
};

// ---------------- sync primitives ----------------
__device__ __forceinline__ void red_release(unsigned* p, unsigned v) {
    asm volatile("red.release.gpu.add.u32 [%0], %1;" :: "l"(p), "r"(v) : "memory");
}
__device__ __forceinline__ unsigned ld_acq(const unsigned* p) {
    unsigned v;
    asm volatile("ld.acquire.gpu.u32 %0, [%1];" : "=r"(v) : "l"(p) : "memory");
    return v;
}
__device__ __forceinline__ void publish(unsigned* p, unsigned v) {
    asm volatile("fence.acq_rel.gpu;" ::: "memory");
    asm volatile("st.relaxed.gpu.u32 [%0], %1;" :: "l"(p), "r"(v) : "memory");
}

// ---------------- math helpers ----------------
__device__ __forceinline__ float2 cmul(float2 a, float2 b) {
    return make_float2(a.x * b.x - a.y * b.y, a.x * b.y + a.y * b.x);
}
__device__ __forceinline__ int chain_perm(int k) {   // CNOT chain = prefix-XOR
    k ^= k >> 1; k ^= k >> 2; k ^= k >> 4;
    return k & 0xFF;
}
__device__ __forceinline__ float rcpf(float x) {
    float r;
    asm("rcp.approx.f32 %0, %1;" : "=f"(r) : "f"(x));
    return r;
}
// sigmoid(x), |x|<=1: odd Taylor deg 9, err <= 2.2e-6
__device__ __forceinline__ float sig_poly(float x) {
    float y = x * x;
    float p = fmaf(y,  2.1356999e-5f, -2.1084600e-4f);
    p = fmaf(y, p,  2.0833333e-3f);
    p = fmaf(y, p, -2.0833333e-2f);
    p = fmaf(y, p,  2.5e-1f);
    return fmaf(x, p, 0.5f);
}
// tanh(x), |x|<~2.8: [7/6] Pade, flattened dependency tree
__device__ __forceinline__ float tanh_pade(float x) {
    float y  = x * x;
    float t1 = fmaf(y, 4725.f, 10395.f);
    float t2 = y + 210.f;
    float y2 = y * y;
    float d  = fmaf(y2, t2, t1);                      // y^3+210y^2+4725y+10395
    float n  = fmaf(y, fmaf(y, 21.f, 1260.f), 10395.f);
    return (x * n) * rcpf(d);
}

// ---------------- init (reset counters each replay) ----------------
__global__ void init_kernel() {
    int i = threadIdx.x;
    if (i < NCH) g_zcnt[i] = 0u;
    if (i == NCH) g_done = 0u;
}

// ---------------- fused kernel ----------------
__global__ void __launch_bounds__(256, 2) fused_kernel(Args a) {
    const int bid  = blockIdx.x;
    const int tid  = threadIdx.x;
    const int warp = tid >> 5, lane = tid & 31;

    // ============================ block 0: consts + scan ============================
    if (bid == 0) {
        __shared__ float2 rot[2][8][2][2];
        __shared__ float2 u0[DIMQ];
        __shared__ float2 u1[DIMQ];
        __shared__ float  rbuf[4][8];
        __shared__ float  s_gate[4][5];   // alpha, R, phi, sW, b0

        const int k   = tid;
        const int pk0 = chain_perm(k);

        for (int g = 0; g < 4; ++g) {
            __syncthreads();
            const float* P = a.P[g];
            if (k < 16) {
                int l = k >> 3, w = k & 7;
                float phi = P[(l * 8 + w) * 3 + 0];
                float th  = P[(l * 8 + w) * 3 + 1];
                float om  = P[(l * 8 + w) * 3 + 2];
                float s, c;
                __sincosf(0.5f * th, &s, &c);
                float hp = 0.5f * (phi + om);
                float hm = 0.5f * (phi - om);
                float2 ep = make_float2(__cosf(hp), -__sinf(hp));
                float2 em = make_float2(__cosf(hm),  __sinf(hm));
                rot[l][w][0][0] = make_float2( ep.x * c,  ep.y * c);
                rot[l][w][0][1] = make_float2(-em.x * s, -em.y * s);
                rot[l][w][1][0] = make_float2( em.x * s, -em.y * s);
                rot[l][w][1][1] = make_float2( ep.x * c, -ep.y * c);
            }
            __syncthreads();

            float2 a0v = make_float2(1.f, 0.f);
            float2 a1v = make_float2(1.f, 0.f);
            #pragma unroll
            for (int w = 0; w < 8; ++w) {
                int kb = (k >> (7 - w)) & 1;
                a0v = cmul(a0v, rot[0][w][kb][0]);
                a1v = cmul(a1v, rot[0][w][kb][(w == 0) ? 1 : 0]);
            }
            u0[pk0] = a0v;
            u1[pk0] = a1v;
            __syncthreads();

            #pragma unroll
            for (int w = 0; w < 8; ++w) {
                int p = 7 - w, m = 1 << p, kb = (k >> p) & 1;
                float2 x0 = u0[k & ~m], x1 = u0[k | m];
                float2 y0 = u1[k & ~m], y1 = u1[k | m];
                __syncthreads();
                float2 r0 = rot[1][w][kb][0];
                float2 r1 = rot[1][w][kb][1];
                u0[k] = make_float2(r0.x * x0.x - r0.y * x0.y + r1.x * x1.x - r1.y * x1.y,
                                    r0.x * x0.y + r0.y * x0.x + r1.x * x1.y + r1.y * x1.x);
                u1[k] = make_float2(r0.x * y0.x - r0.y * y0.y + r1.x * y1.x - r1.y * y1.y,
                                    r0.x * y0.y + r0.y * y0.x + r1.x * y1.y + r1.y * y1.x);
                __syncthreads();
            }

            float2 c0 = u0[k], c1 = u1[k];
            __syncthreads();
            u0[pk0] = c0; u1[pk0] = c1;
            __syncthreads();
            c0 = u0[k]; c1 = u1[k];

            float z0 = (k < 128) ? 1.f : -1.f;
            float A  = z0 * (c0.x * c0.x + c0.y * c0.y);
            float Bv = z0 * (c1.x * c1.x + c1.y * c1.y);
            float Cv = -2.f * z0 * (c0.y * c1.x - c0.x * c1.y);
            const float* W = a.W[g];
            float sw = W[512 + k] + W[768 + k];

            float vals[4] = {A, Bv, Cv, sw};
            #pragma unroll
            for (int i = 0; i < 4; ++i) {
                float xv = vals[i];
                #pragma unroll
                for (int off = 16; off; off >>= 1)
                    xv += __shfl_xor_sync(0xffffffffu, xv, off);
                if (lane == 0) rbuf[i][warp] = xv;
            }
            __syncthreads();
            if (k == 0) {
                float t[4];
                #pragma unroll
                for (int i = 0; i < 4; ++i) {
                    float s = 0.f;
                    #pragma unroll
                    for (int wv = 0; wv < 8; ++wv) s += rbuf[i][wv];
                    t[i] = s;
                }
                float alpha = 0.5f * (t[0] + t[1]);
                float beta  = 0.5f * (t[0] - t[1]);
                float gamma = 0.5f * t[2];
                float R     = sqrtf(beta * beta + gamma * gamma);
                float phi   = (R > 0.f) ? atan2f(gamma, beta) : 0.f;
                s_gate[g][0] = alpha;
                s_gate[g][1] = R;
                s_gate[g][2] = phi;
                s_gate[g][3] = t[3];
                s_gate[g][4] = a.b[g][0];
            }
        }
        __syncthreads();

        if (tid >= BATCH) return;   // warps 4-7 of block 0 are done

        // -------- scalar scan (threads 0..127), chunked, credit-gated --------
        const int b = tid;
        const float af = s_gate[0][0], Rf = s_gate[0][1], swf = s_gate[0][3];
        const float ai = s_gate[1][0], Ri = s_gate[1][1], swi = s_gate[1][3];
        const float ag = s_gate[2][0], Rg = s_gate[2][1], swg = s_gate[2][3];
        const float ao = s_gate[3][0], Ro = s_gate[3][1], swo = s_gate[3][3];
        const float tbf = s_gate[0][4] - s_gate[0][2];
        const float tbi = s_gate[1][4] - s_gate[1][2];
        const float tbg = s_gate[2][4] - s_gate[2][2];
        const float tbo = s_gate[3][4] - s_gate[3][2];

        float h = 0.f, cc = 0.f;

        #define QSTEP(ZV, T) { \
            float vf = __cosf(fmaf(h, swf, (ZV).x)); \
            float vi = __cosf(fmaf(h, swi, (ZV).y)); \
            float vg = __cosf(fmaf(h, swg, (ZV).z)); \
            float vo = __cosf(fmaf(h, swo, (ZV).w)); \
            float ff = sig_poly(fmaf(Rf, vf, af)); \
            float ii = sig_poly(fmaf(Ri, vi, ai)); \
            float gg = tanh_pade(fmaf(Rg, vg, ag)); \
            float oo = sig_poly(fmaf(Ro, vo, ao)); \
            cc = fmaf(ff, cc, ii * gg); \
            h  = oo * tanh_pade(cc); \
            g_h[(T) * BATCH + b] = h; }

        for (int c = 0; c < NCH; ++c) {
            while (ld_acq(&g_zcnt[c]) < (unsigned)CHROWS) {}   // 4 warps only

            const int tbase = c * CH_T;
            float4 zb[4], zn[4];
            #pragma unroll
            for (int j = 0; j < 4; ++j) {
                float4 z = g_z[(tbase + j) * BATCH + b];
                zb[j] = make_float4(z.x + tbf, z.y + tbi, z.z + tbg, z.w + tbo);
            }
            #pragma unroll
            for (int j = 0; j < 4; ++j) {
                float4 z = g_z[(tbase + 4 + j) * BATCH + b];
                zn[j] = make_float4(z.x + tbf, z.y + tbi, z.z + tbg, z.w + tbo);
            }
            for (int g4 = 0; g4 < CH_T; g4 += 4) {
                float4 znn[4];
                const bool more = (g4 + 8 < CH_T);
                if (more) {   // 8-step-deep prefetch
                    #pragma unroll
                    for (int j = 0; j < 4; ++j) {
                        float4 z = g_z[(tbase + g4 + 8 + j) * BATCH + b];
                        znn[j] = make_float4(z.x + tbf, z.y + tbi, z.z + tbg, z.w + tbo);
                    }
                }
                QSTEP(zb[0], tbase + g4 + 0);
                QSTEP(zb[1], tbase + g4 + 1);
                QSTEP(zb[2], tbase + g4 + 2);
                QSTEP(zb[3], tbase + g4 + 3);
                zb[0] = zn[0]; zb[1] = zn[1]; zb[2] = zn[2]; zb[3] = zn[3];
                if (more) { zn[0] = znn[0]; zn[1] = znn[1]; zn[2] = znn[2]; zn[3] = znn[3]; }
            }
            if (c == NCH - 1) g_cfin[b] = cc;

            asm volatile("bar.sync 1, 128;" ::: "memory");   // all 4 scan warps done
            if (tid == 0) publish(&g_done, (unsigned)(c + 1));
        }
        #undef QSTEP
        return;
    }

    // ============================ workers ============================
    // -------- PHASE 1: projection, CHUNK-MAJOR order + credits --------
    {
        const int gw = (bid - 1) * 8 + warp;   // 0 .. Wp-1
        const float4* x4 = reinterpret_cast<const float4*>(a.x);

        float4 wv0[4], wv1[4], wv2[4], wv3[4];
        {
            const float4* W0 = reinterpret_cast<const float4*>(a.W[0]);
            const float4* W1 = reinterpret_cast<const float4*>(a.W[1]);
            const float4* W2 = reinterpret_cast<const float4*>(a.W[2]);
            const float4* W3 = reinterpret_cast<const float4*>(a.W[3]);
            #pragma unroll
            for (int it = 0; it < 4; ++it) {
                int e4 = it * 32 + lane;
                wv0[it] = W0[e4]; wv1[it] = W1[e4];
                wv2[it] = W2[e4]; wv3[it] = W3[e4];
            }
        }

        for (int c = 0; c < NCH; ++c) {
            const int cbase = c * CHROWS;
            int done = 0;
            for (int r = cbase + gw; r < cbase + CHROWS; r += a.Wp) {
                const float4* xr = x4 + (size_t)r * 128;
                float s0 = 0.f, s1 = 0.f, s2 = 0.f, s3 = 0.f;
                #pragma unroll
                for (int it = 0; it < 4; ++it) {
                    float4 xv = xr[it * 32 + lane];
                    s0 = fmaf(xv.x, wv0[it].x, s0); s0 = fmaf(xv.y, wv0[it].y, s0);
                    s0 = fmaf(xv.z, wv0[it].z, s0); s0 = fmaf(xv.w, wv0[it].w, s0);
                    s1 = fmaf(xv.x, wv1[it].x, s1); s1 = fmaf(xv.y, wv1[it].y, s1);
                    s1 = fmaf(xv.z, wv1[it].z, s1); s1 = fmaf(xv.w, wv1[it].w, s1);
                    s2 = fmaf(xv.x, wv2[it].x, s2); s2 = fmaf(xv.y, wv2[it].y, s2);
                    s2 = fmaf(xv.z, wv2[it].z, s2); s2 = fmaf(xv.w, wv2[it].w, s2);
                    s3 = fmaf(xv.x, wv3[it].x, s3); s3 = fmaf(xv.y, wv3[it].y, s3);
                    s3 = fmaf(xv.z, wv3[it].z, s3); s3 = fmaf(xv.w, wv3[it].w, s3);
                }
                #pragma unroll
                for (int off = 16; off; off >>= 1) {
                    s0 += __shfl_xor_sync(0xffffffffu, s0, off);
                    s1 += __shfl_xor_sync(0xffffffffu, s1, off);
                    s2 += __shfl_xor_sync(0xffffffffu, s2, off);
                    s3 += __shfl_xor_sync(0xffffffffu, s3, off);
                }
                if (lane == 0) g_z[r] = make_float4(s0, s1, s2, s3);
                ++done;
            }
            if (lane == 0 && done) red_release(&g_zcnt[c], (unsigned)done);
        }
    }

    // -------- PHASE 2: broadcast, chunk-by-chunk gated on g_done --------
    {
        float4* out = a.out;
        const int stride = (a.G - 1) * 256;
        const int self   = (bid - 1) * 256 + tid;

        for (int c = 0; c < NCH; ++c) {
            if (tid == 0) {
                while (ld_acq(&g_done) < (unsigned)(c + 1)) __nanosleep(128);
            }
            __syncthreads();
            const int base = c * REG4;
            const int end  = base + REG4;
            #pragma unroll 2
            for (int i = base + self; i < end; i += stride) {
                float v = g_h[i >> 7];
                out[i] = make_float4(v, v, v, v);
            }
        }
        // hx + cx
        const int base = NCH * REG4;   // == ROWS*128
        for (int i = base + self; i < a.n4; i += stride) {
            int row = i >> 7;
            float v;
            if (row < ROWS + BATCH) v = g_h[row - BATCH];            // hx = h at t=255
            else                    v = g_cfin[row - ROWS - BATCH];  // cx
            out[i] = make_float4(v, v, v, v);
        }
    }
}

// ---------------- launch ----------------
extern "C" void kernel_launch(void* const* d_in, const int* in_sizes, int n_in,
                              void* d_out, int out_size) {
    static int s_sm = -1;
    if (s_sm < 0) {
        int dev = 0;
        cudaGetDevice(&dev);
        cudaDeviceGetAttribute(&s_sm, cudaDevAttrMultiProcessorCount, dev);
        if (s_sm <= 0) s_sm = 148;
    }
    const int G  = 2 * s_sm;            // all blocks resident
    const int Wp = (G - 1) * 8;

    Args a;
    a.x = (const float*)d_in[0];
    a.W[0] = (const float*)d_in[1];  a.b[0] = (const float*)d_in[2];  a.P[0] = (const float*)d_in[3];
    a.W[1] = (const float*)d_in[4];  a.b[1] = (const float*)d_in[5];  a.P[1] = (const float*)d_in[6];
    a.W[2] = (const float*)d_in[7];  a.b[2] = (const float*)d_in[8];  a.P[2] = (const float*)d_in[9];
    a.W[3] = (const float*)d_in[10]; a.b[3] = (const float*)d_in[11]; a.P[3] = (const float*)d_in[12];
    a.out = (float4*)d_out;
    a.G   = G;
    a.Wp  = Wp;
    a.n4  = out_size / 4;

    init_kernel<<<1, 32>>>();
    fused_kernel<<<G, 256>>>(a);
}

// round 9
// speedup vs baseline: 2.9914x; 1.3439x over previous
#include <cuda_runtime.h>
#include <cstdint>

// ---------------------------------------------------------------------------
// QLSTM fused persistent kernel, v5: smem-staged scan feed.
//   * each gate uses only W[0,:]  -> theta is a scalar per batch element
//   * _expval(theta,U) = alpha + R*cos(theta - phi), E in [-1,1]
//   * f,i,g,o scalars per row -> c[b,:], h[b,:] uniform over hidden dim
// Roles:
//   block 0  warps 0-3 : 128 scalar scans, fed from SHARED MEMORY only
//            warps 4-7 : z-stagers: gmem -> smem ring (4 bufs x 8 steps),
//                        bias folded during copy
//   blocks 1..G-1      : chunk-major projection (credits) then chunk-by-chunk
//                        broadcast gated on g_done
// Scan never waits on L2/DRAM latency: stagers absorb it with deep MLP.
// ---------------------------------------------------------------------------

#define T_STEPS 256
#define BATCH   128
#define ROWS    (T_STEPS * BATCH)     // 32768
#define DIMQ    256
#define NCH     8
#define CH_T    32                    // scan steps per credit/bcast chunk
#define CHROWS  (CH_T * BATCH)        // 4096 z-rows per chunk
#define REG4    (CHROWS * 128)        // float4 of output per chunk = 524288
#define SEQ_T   8                     // steps per smem buffer
#define NSEQ    (T_STEPS / SEQ_T)     // 32
#define NBUF    4                     // ring depth (4 x 8 x 128 x 16B = 64 KB)

__device__ float4   g_z[ROWS];        // per (t,b): x-projection per gate
__device__ float    g_h[ROWS];        // h scalar per (t,b)
__device__ float    g_cfin[BATCH];    // final c per b
__device__ unsigned g_zcnt[NCH];      // z rows completed per chunk (target 4096)
__device__ unsigned g_done;           // scan chunks completed (target 8)

struct Args {
    const float* x;
    const float* W[4];
    const float* b[4];
    const float* P[4];
    float4* out;
    int G;     // grid size
    int Wp;    // proj warps = (G-1)*8
    int n4;    // out_size / 4
};

// ---------------- sync primitives ----------------
__device__ __forceinline__ void red_release(unsigned* p, unsigned v) {
    asm volatile("red.release.gpu.add.u32 [%0], %1;" :: "l"(p), "r"(v) : "memory");
}
__device__ __forceinline__ unsigned ld_acq(const unsigned* p) {
    unsigned v;
    asm volatile("ld.acquire.gpu.u32 %0, [%1];" : "=r"(v) : "l"(p) : "memory");
    return v;
}
__device__ __forceinline__ void publish(unsigned* p, unsigned v) {
    asm volatile("fence.acq_rel.gpu;" ::: "memory");
    asm volatile("st.relaxed.gpu.u32 [%0], %1;" :: "l"(p), "r"(v) : "memory");
}

// ---------------- math helpers ----------------
__device__ __forceinline__ float2 cmul(float2 a, float2 b) {
    return make_float2(a.x * b.x - a.y * b.y, a.x * b.y + a.y * b.x);
}
__device__ __forceinline__ int chain_perm(int k) {   // CNOT chain = prefix-XOR
    k ^= k >> 1; k ^= k >> 2; k ^= k >> 4;
    return k & 0xFF;
}
__device__ __forceinline__ float rcpf(float x) {
    float r;
    asm("rcp.approx.f32 %0, %1;" : "=f"(r) : "f"(x));
    return r;
}
// sigmoid(x), |x|<=1: odd Taylor deg 9, err <= 2.2e-6
__device__ __forceinline__ float sig_poly(float x) {
    float y = x * x;
    float p = fmaf(y,  2.1356999e-5f, -2.1084600e-4f);
    p = fmaf(y, p,  2.0833333e-3f);
    p = fmaf(y, p, -2.0833333e-2f);
    p = fmaf(y, p,  2.5e-1f);
    return fmaf(x, p, 0.5f);
}
// tanh(x), |x|<~2.8: [7/6] Pade, flattened dependency tree
__device__ __forceinline__ float tanh_pade(float x) {
    float y  = x * x;
    float t1 = fmaf(y, 4725.f, 10395.f);
    float t2 = y + 210.f;
    float y2 = y * y;
    float d  = fmaf(y2, t2, t1);
    float n  = fmaf(y, fmaf(y, 21.f, 1260.f), 10395.f);
    return (x * n) * rcpf(d);
}

// ---------------- init (reset counters each replay) ----------------
__global__ void init_kernel() {
    int i = threadIdx.x;
    if (i < NCH) g_zcnt[i] = 0u;
    if (i == NCH) g_done = 0u;
}

// ---------------- fused kernel ----------------
__global__ void __launch_bounds__(256, 2) fused_kernel(Args a) {
    extern __shared__ float4 s_z[];   // [NBUF][SEQ_T][BATCH] = 64 KB (block 0 only)

    const int bid  = blockIdx.x;
    const int tid  = threadIdx.x;
    const int warp = tid >> 5, lane = tid & 31;

    // ============================ block 0: consts + staged scan ============================
    if (bid == 0) {
        __shared__ float2 rot[2][8][2][2];
        __shared__ float2 u0[DIMQ];
        __shared__ float2 u1[DIMQ];
        __shared__ float  rbuf[4][8];
        __shared__ float  s_gate[4][5];   // alpha, R, phi, sW, b0
        __shared__ int    s_prod;         // staged buffers published
        __shared__ int    s_cons;         // staged buffers consumed

        const int k   = tid;
        const int pk0 = chain_perm(k);
        if (tid == 0) { s_prod = 0; s_cons = 0; }

        // -------- gate constants (all 256 threads, 4 gates) --------
        for (int g = 0; g < 4; ++g) {
            __syncthreads();
            const float* P = a.P[g];
            if (k < 16) {
                int l = k >> 3, w = k & 7;
                float phi = P[(l * 8 + w) * 3 + 0];
                float th  = P[(l * 8 + w) * 3 + 1];
                float om  = P[(l * 8 + w) * 3 + 2];
                float s, c;
                __sincosf(0.5f * th, &s, &c);
                float hp = 0.5f * (phi + om);
                float hm = 0.5f * (phi - om);
                float2 ep = make_float2(__cosf(hp), -__sinf(hp));
                float2 em = make_float2(__cosf(hm),  __sinf(hm));
                rot[l][w][0][0] = make_float2( ep.x * c,  ep.y * c);
                rot[l][w][0][1] = make_float2(-em.x * s, -em.y * s);
                rot[l][w][1][0] = make_float2( em.x * s, -em.y * s);
                rot[l][w][1][1] = make_float2( ep.x * c, -ep.y * c);
            }
            __syncthreads();

            float2 a0v = make_float2(1.f, 0.f);
            float2 a1v = make_float2(1.f, 0.f);
            #pragma unroll
            for (int w = 0; w < 8; ++w) {
                int kb = (k >> (7 - w)) & 1;
                a0v = cmul(a0v, rot[0][w][kb][0]);
                a1v = cmul(a1v, rot[0][w][kb][(w == 0) ? 1 : 0]);
            }
            u0[pk0] = a0v;
            u1[pk0] = a1v;
            __syncthreads();

            #pragma unroll
            for (int w = 0; w < 8; ++w) {
                int p = 7 - w, m = 1 << p, kb = (k >> p) & 1;
                float2 x0 = u0[k & ~m], x1 = u0[k | m];
                float2 y0 = u1[k & ~m], y1 = u1[k | m];
                __syncthreads();
                float2 r0 = rot[1][w][kb][0];
                float2 r1 = rot[1][w][kb][1];
                u0[k] = make_float2(r0.x * x0.x - r0.y * x0.y + r1.x * x1.x - r1.y * x1.y,
                                    r0.x * x0.y + r0.y * x0.x + r1.x * x1.y + r1.y * x1.x);
                u1[k] = make_float2(r0.x * y0.x - r0.y * y0.y + r1.x * y1.x - r1.y * y1.y,
                                    r0.x * y0.y + r0.y * y0.x + r1.x * y1.y + r1.y * y1.x);
                __syncthreads();
            }

            float2 c0 = u0[k], c1 = u1[k];
            __syncthreads();
            u0[pk0] = c0; u1[pk0] = c1;
            __syncthreads();
            c0 = u0[k]; c1 = u1[k];

            float z0 = (k < 128) ? 1.f : -1.f;
            float A  = z0 * (c0.x * c0.x + c0.y * c0.y);
            float Bv = z0 * (c1.x * c1.x + c1.y * c1.y);
            float Cv = -2.f * z0 * (c0.y * c1.x - c0.x * c1.y);
            const float* W = a.W[g];
            float sw = W[512 + k] + W[768 + k];

            float vals[4] = {A, Bv, Cv, sw};
            #pragma unroll
            for (int i = 0; i < 4; ++i) {
                float xv = vals[i];
                #pragma unroll
                for (int off = 16; off; off >>= 1)
                    xv += __shfl_xor_sync(0xffffffffu, xv, off);
                if (lane == 0) rbuf[i][warp] = xv;
            }
            __syncthreads();
            if (k == 0) {
                float t[4];
                #pragma unroll
                for (int i = 0; i < 4; ++i) {
                    float s = 0.f;
                    #pragma unroll
                    for (int wv = 0; wv < 8; ++wv) s += rbuf[i][wv];
                    t[i] = s;
                }
                float alpha = 0.5f * (t[0] + t[1]);
                float beta  = 0.5f * (t[0] - t[1]);
                float gamma = 0.5f * t[2];
                float R     = sqrtf(beta * beta + gamma * gamma);
                float phi   = (R > 0.f) ? atan2f(gamma, beta) : 0.f;
                s_gate[g][0] = alpha;
                s_gate[g][1] = R;
                s_gate[g][2] = phi;
                s_gate[g][3] = t[3];
                s_gate[g][4] = a.b[g][0];
            }
        }
        __syncthreads();

        volatile int* vprod = &s_prod;
        volatile int* vcons = &s_cons;

        if (tid >= BATCH) {
            // ================= warps 4-7: z-stagers (gmem -> smem ring) =================
            const int p = tid - BATCH;   // 0..127
            const float tbf = s_gate[0][4] - s_gate[0][2];
            const float tbi = s_gate[1][4] - s_gate[1][2];
            const float tbg = s_gate[2][4] - s_gate[2][2];
            const float tbo = s_gate[3][4] - s_gate[3][2];

            for (int seq = 0; seq < NSEQ; ++seq) {
                if ((seq & 3) == 0) {    // new credit chunk of 32 steps
                    const int c = seq >> 2;
                    while (ld_acq(&g_zcnt[c]) < (unsigned)CHROWS) {}
                }
                while (*vcons < seq - (NBUF - 1)) {}   // ring space

                float4 zb[SEQ_T];
                #pragma unroll
                for (int s = 0; s < SEQ_T; ++s)
                    zb[s] = g_z[(seq * SEQ_T + s) * BATCH + p];   // coalesced, 8 in flight
                float4* dst = &s_z[(size_t)(seq & (NBUF - 1)) * SEQ_T * BATCH + p];
                #pragma unroll
                for (int s = 0; s < SEQ_T; ++s) {
                    float4 z = zb[s];
                    dst[s * BATCH] = make_float4(z.x + tbf, z.y + tbi, z.z + tbg, z.w + tbo);
                }
                asm volatile("bar.sync 2, 128;" ::: "memory");   // all stagers done (drains STS)
                if (p == 0) *vprod = seq + 1;
            }
            return;
        }

        // ================= warps 0-3: scalar scan from smem =================
        const int b = tid;
        const float af = s_gate[0][0], Rf = s_gate[0][1], swf = s_gate[0][3];
        const float ai = s_gate[1][0], Ri = s_gate[1][1], swi = s_gate[1][3];
        const float ag = s_gate[2][0], Rg = s_gate[2][1], swg = s_gate[2][3];
        const float ao = s_gate[3][0], Ro = s_gate[3][1], swo = s_gate[3][3];

        float h = 0.f, cc = 0.f;

        #define QSTEP(ZV, T) { \
            float vf = __cosf(fmaf(h, swf, (ZV).x)); \
            float vi = __cosf(fmaf(h, swi, (ZV).y)); \
            float vg = __cosf(fmaf(h, swg, (ZV).z)); \
            float vo = __cosf(fmaf(h, swo, (ZV).w)); \
            float ff = sig_poly(fmaf(Rf, vf, af)); \
            float ii = sig_poly(fmaf(Ri, vi, ai)); \
            float gg = tanh_pade(fmaf(Rg, vg, ag)); \
            float oo = sig_poly(fmaf(Ro, vo, ao)); \
            cc = fmaf(ff, cc, ii * gg); \
            h  = oo * tanh_pade(cc); \
            g_h[(T) * BATCH + b] = h; }

        for (int seq = 0; seq < NSEQ; ++seq) {
            while (*vprod < seq + 1) {}              // smem spin, usually passes
            const float4* src = &s_z[(size_t)(seq & (NBUF - 1)) * SEQ_T * BATCH + b];
            float4 zv[SEQ_T];
            #pragma unroll
            for (int s = 0; s < SEQ_T; ++s) zv[s] = src[s * BATCH];   // LDS, hidden
            const int tbase = seq * SEQ_T;
            #pragma unroll
            for (int s = 0; s < SEQ_T; ++s) QSTEP(zv[s], tbase + s);

            if (seq == NSEQ - 1) g_cfin[b] = cc;
            asm volatile("bar.sync 1, 128;" ::: "memory");   // all scan warps done
            if (tid == 0) {
                *vcons = seq + 1;
                if ((seq & 3) == 3) publish(&g_done, (unsigned)((seq >> 2) + 1));
            }
        }
        #undef QSTEP
        return;
    }

    // ============================ workers ============================
    // -------- PHASE 1: projection, CHUNK-MAJOR order + credits --------
    {
        const int gw = (bid - 1) * 8 + warp;   // 0 .. Wp-1
        const float4* x4 = reinterpret_cast<const float4*>(a.x);

        float4 wv0[4], wv1[4], wv2[4], wv3[4];
        {
            const float4* W0 = reinterpret_cast<const float4*>(a.W[0]);
            const float4* W1 = reinterpret_cast<const float4*>(a.W[1]);
            const float4* W2 = reinterpret_cast<const float4*>(a.W[2]);
            const float4* W3 = reinterpret_cast<const float4*>(a.W[3]);
            #pragma unroll
            for (int it = 0; it < 4; ++it) {
                int e4 = it * 32 + lane;
                wv0[it] = W0[e4]; wv1[it] = W1[e4];
                wv2[it] = W2[e4]; wv3[it] = W3[e4];
            }
        }

        for (int c = 0; c < NCH; ++c) {
            const int cbase = c * CHROWS;
            int done = 0;
            for (int r = cbase + gw; r < cbase + CHROWS; r += a.Wp) {
                const float4* xr = x4 + (size_t)r * 128;
                float s0 = 0.f, s1 = 0.f, s2 = 0.f, s3 = 0.f;
                #pragma unroll
                for (int it = 0; it < 4; ++it) {
                    float4 xv = xr[it * 32 + lane];
                    s0 = fmaf(xv.x, wv0[it].x, s0); s0 = fmaf(xv.y, wv0[it].y, s0);
                    s0 = fmaf(xv.z, wv0[it].z, s0); s0 = fmaf(xv.w, wv0[it].w, s0);
                    s1 = fmaf(xv.x, wv1[it].x, s1); s1 = fmaf(xv.y, wv1[it].y, s1);
                    s1 = fmaf(xv.z, wv1[it].z, s1); s1 = fmaf(xv.w, wv1[it].w, s1);
                    s2 = fmaf(xv.x, wv2[it].x, s2); s2 = fmaf(xv.y, wv2[it].y, s2);
                    s2 = fmaf(xv.z, wv2[it].z, s2); s2 = fmaf(xv.w, wv2[it].w, s2);
                    s3 = fmaf(xv.x, wv3[it].x, s3); s3 = fmaf(xv.y, wv3[it].y, s3);
                    s3 = fmaf(xv.z, wv3[it].z, s3); s3 = fmaf(xv.w, wv3[it].w, s3);
                }
                #pragma unroll
                for (int off = 16; off; off >>= 1) {
                    s0 += __shfl_xor_sync(0xffffffffu, s0, off);
                    s1 += __shfl_xor_sync(0xffffffffu, s1, off);
                    s2 += __shfl_xor_sync(0xffffffffu, s2, off);
                    s3 += __shfl_xor_sync(0xffffffffu, s3, off);
                }
                if (lane == 0) g_z[r] = make_float4(s0, s1, s2, s3);
                ++done;
            }
            if (lane == 0 && done) red_release(&g_zcnt[c], (unsigned)done);
        }
    }

    // -------- PHASE 2: broadcast, chunk-by-chunk gated on g_done --------
    {
        float4* out = a.out;
        const int stride = (a.G - 1) * 256;
        const int self   = (bid - 1) * 256 + tid;

        for (int c = 0; c < NCH; ++c) {
            if (tid == 0) {
                while (ld_acq(&g_done) < (unsigned)(c + 1)) __nanosleep(128);
            }
            __syncthreads();
            const int base = c * REG4;
            const int end  = base + REG4;
            #pragma unroll 2
            for (int i = base + self; i < end; i += stride) {
                float v = g_h[i >> 7];
                out[i] = make_float4(v, v, v, v);
            }
        }
        // hx + cx
        const int base = NCH * REG4;   // == ROWS*128
        for (int i = base + self; i < a.n4; i += stride) {
            int row = i >> 7;
            float v;
            if (row < ROWS + BATCH) v = g_h[row - BATCH];            // hx = h at t=255
            else                    v = g_cfin[row - ROWS - BATCH];  // cx
            out[i] = make_float4(v, v, v, v);
        }
    }
}

// ---------------- launch ----------------
extern "C" void kernel_launch(void* const* d_in, const int* in_sizes, int n_in,
                              void* d_out, int out_size) {
    static int s_sm = -1;
    const int DYN = NBUF * SEQ_T * BATCH * (int)sizeof(float4);   // 64 KB
    if (s_sm < 0) {
        int dev = 0;
        cudaGetDevice(&dev);
        cudaDeviceGetAttribute(&s_sm, cudaDevAttrMultiProcessorCount, dev);
        if (s_sm <= 0) s_sm = 148;
        cudaFuncSetAttribute(fused_kernel,
                             cudaFuncAttributeMaxDynamicSharedMemorySize, DYN);
    }
    const int G  = 2 * s_sm;            // all blocks resident
    const int Wp = (G - 1) * 8;

    Args a;
    a.x = (const float*)d_in[0];
    a.W[0] = (const float*)d_in[1];  a.b[0] = (const float*)d_in[2];  a.P[0] = (const float*)d_in[3];
    a.W[1] = (const float*)d_in[4];  a.b[1] = (const float*)d_in[5];  a.P[1] = (const float*)d_in[6];
    a.W[2] = (const float*)d_in[7];  a.b[2] = (const float*)d_in[8];  a.P[2] = (const float*)d_in[9];
    a.W[3] = (const float*)d_in[10]; a.b[3] = (const float*)d_in[11]; a.P[3] = (const float*)d_in[12];
    a.out = (float4*)d_out;
    a.G   = G;
    a.Wp  = Wp;
    a.n4  = out_size / 4;

    init_kernel<<<1, 32>>>();
    fused_kernel<<<G, 256, DYN>>>(a);
}